// round 12
// baseline (speedup 1.0000x reference)
#include <cuda_runtime.h>
#include <cstdint>

// TrueHigherOrderAttention — degenerate-mask reduction.
// The reference mask forces j==i and k==i, so the (j,k) softmax is an exact
// one-hot at (i,i,i):   out = ((x @ Wv1^T) .* (x @ Wv2^T)) @ Wc^T
//
// R10 = R9 (21.2us: double-buffered smem, fragment software-pipeline,
// m16n8k8 3xTF32, BLK=258) + PARITY-SPLIT ACCUMULATORS: each decomposition
// term accumulates into an even-step and an odd-step register set, doubling
// the number of independent MMA dependency chains per warp (3->6 / 6->12)
// so the ~30-cyc accumulate-RAW latency no longer caps issue.

constexpr int T    = 256;
constexpr int C    = 512;
constexpr int KC   = 64;
constexpr int NCH  = 8;          // 512 / 64
constexpr int BLK  = 258;        // words per 8-k block (32 rows x 8 + pad 2)
constexpr int TIER = 8 * BLK;    // hi -> lo offset within a tile

__device__ float g_tmp[T * C];

__device__ __forceinline__ uint32_t f2tf32(float x)
{
    uint32_t r;
    asm("cvt.rna.tf32.f32 %0, %1;" : "=r"(r) : "f"(x));
    return r;
}

__device__ __forceinline__ void mma8(float* d, const uint32_t* a, const uint32_t* b)
{
    asm("mma.sync.aligned.m16n8k8.row.col.f32.tf32.tf32.f32 "
        "{%0,%1,%2,%3}, {%4,%5,%6,%7}, {%8,%9}, {%0,%1,%2,%3};"
        : "+f"(d[0]), "+f"(d[1]), "+f"(d[2]), "+f"(d[3])
        : "r"(a[0]), "r"(a[1]), "r"(a[2]), "r"(a[3]),
          "r"(b[0]), "r"(b[1]));
}

// OUT = (X @ W1^T) [ .* (X @ W2^T) if DUAL ]  on a 32x32 tile, 3xTF32.
// X: [M x C] row-major; W: [C x C] row-major (output col n = row n of W).
template <bool DUAL>
__global__ __launch_bounds__(256)
void gemm_mma_kernel(const float* __restrict__ X,
                     const float* __restrict__ W1,
                     const float* __restrict__ W2,
                     float* __restrict__ OUT)
{
    extern __shared__ uint32_t sm[];
    constexpr int NTILE = DUAL ? 3 : 2;
    constexpr int BUFW  = 2 * NTILE * TIER;   // words per double-buffer half

    const int i0   = blockIdx.x * 32;
    const int n0   = blockIdx.y * 32;
    const int tid  = threadIdx.x;
    const int lane = tid & 31;
    const int wid  = tid >> 5;

    // ---- loader mapping (conflict-free STS with BLK=258) ----
    const int lrow = tid >> 3;   // 0..31
    const int j0   = tid & 7;    // float4 quad; +8 on second iter

    float4 xr[2], w1r[2], w2r[2];
    auto gload = [&](int kb) {
#pragma unroll
        for (int it = 0; it < 2; it++) {
            const int j = j0 + 8 * it;
            xr [it] = *(const float4*)&X [(i0 + lrow) * C + kb + 4 * j];
            w1r[it] = *(const float4*)&W1[(n0 + lrow) * C + kb + 4 * j];
            if (DUAL)
                w2r[it] = *(const float4*)&W2[(n0 + lrow) * C + kb + 4 * j];
        }
    };

    auto stile = [&](uint32_t* base, const float4& v, int j) {
        uint32_t* dst = base + (j >> 1) * BLK + lrow * 8 + (j & 1);
        const float vv[4] = {v.x, v.y, v.z, v.w};
#pragma unroll
        for (int cc = 0; cc < 4; cc++) {
            const uint32_t hi = f2tf32(vv[cc]);
            dst[2 * cc]        = hi;
            dst[TIER + 2 * cc] = __float_as_uint(vv[cc] - __uint_as_float(hi));
        }
    };

    auto split_sts = [&](uint32_t* buf) {
#pragma unroll
        for (int it = 0; it < 2; it++) {
            const int j = j0 + 8 * it;
            stile(buf,            xr [it], j);
            stile(buf + 2 * TIER, w1r[it], j);
            if (DUAL) stile(buf + 4 * TIER, w2r[it], j);
        }
    };

    // ---- compute mapping: 8 warps = 2(m) x 4(n); warp tile m16 x n8 ----
    const int M0 = (wid >> 2) * 16;
    const int N0 = (wid & 3) * 8;
    const int ar = (M0 + (lane >> 2)) * 8 + 2 * (lane & 3);
    const int br = (N0 + (lane >> 2)) * 8 + 2 * (lane & 3);

    struct Frag {
        uint32_t Ah[4], Al[4], B1h[2], B1l[2], B2h[2], B2l[2];
    };
    Frag fr[2];

    auto ldfrag = [&](const uint32_t* buf, int s, Frag& f) {
        const int o = s * BLK;
        const uint2 h02 = *(const uint2*)&buf[o + ar];
        const uint2 h13 = *(const uint2*)&buf[o + ar + 64];
        const uint2 l02 = *(const uint2*)&buf[TIER + o + ar];
        const uint2 l13 = *(const uint2*)&buf[TIER + o + ar + 64];
        f.Ah[0] = h02.x; f.Ah[1] = h13.x; f.Ah[2] = h02.y; f.Ah[3] = h13.y;
        f.Al[0] = l02.x; f.Al[1] = l13.x; f.Al[2] = l02.y; f.Al[3] = l13.y;
        const uint2 b1h = *(const uint2*)&buf[2 * TIER + o + br];
        const uint2 b1l = *(const uint2*)&buf[3 * TIER + o + br];
        f.B1h[0] = b1h.x; f.B1h[1] = b1h.y;
        f.B1l[0] = b1l.x; f.B1l[1] = b1l.y;
        if (DUAL) {
            const uint2 b2h = *(const uint2*)&buf[4 * TIER + o + br];
            const uint2 b2l = *(const uint2*)&buf[5 * TIER + o + br];
            f.B2h[0] = b2h.x; f.B2h[1] = b2h.y;
            f.B2l[0] = b2l.x; f.B2l[1] = b2l.y;
        }
    };

    // parity-split accumulators: [step parity][term][4]
    float p[2][3][4] = {}, q[2][3][4] = {};

    // ---- prologue: fill buffer 0 ----
    gload(0);
    split_sts(sm);
    __syncthreads();

    for (int ch = 0; ch < NCH; ch++) {
        uint32_t* buf = sm + (ch & 1) * BUFW;
        if (ch + 1 < NCH) gload((ch + 1) * KC);   // LDG early, long latency

        ldfrag(buf, 0, fr[0]);
#pragma unroll
        for (int s = 0; s < 8; s++) {
            if (s < 7) ldfrag(buf, s + 1, fr[(s + 1) & 1]);
            Frag& f = fr[s & 1];
            const int par = s & 1;
            mma8(p[par][0], f.Ah, f.B1h);
            if (DUAL) mma8(q[par][0], f.Ah, f.B2h);
            mma8(p[par][1], f.Ah, f.B1l);
            if (DUAL) mma8(q[par][1], f.Ah, f.B2l);
            mma8(p[par][2], f.Al, f.B1h);
            if (DUAL) mma8(q[par][2], f.Al, f.B2h);
        }

        if (ch + 1 < NCH) {
            split_sts(sm + ((ch + 1) & 1) * BUFW);
            __syncthreads();
        }
    }

    // ---- epilogue: merge parities + decomposition terms, product, store ----
    float P[4], Q[4];
#pragma unroll
    for (int i = 0; i < 4; i++) {
        P[i] = (p[0][0][i] + p[1][0][i])
             + (p[0][1][i] + p[1][1][i])
             + (p[0][2][i] + p[1][2][i]);
        if (DUAL)
            Q[i] = (q[0][0][i] + q[1][0][i])
                 + (q[0][1][i] + q[1][1][i])
                 + (q[0][2][i] + q[1][2][i]);
    }
    const int row = i0 + M0 + (lane >> 2);
    const int col = n0 + N0 + 2 * (lane & 3);
    float2 v0, v1;
    if (DUAL) {
        v0 = make_float2(P[0] * Q[0], P[1] * Q[1]);
        v1 = make_float2(P[2] * Q[2], P[3] * Q[3]);
    } else {
        v0 = make_float2(P[0], P[1]);
        v1 = make_float2(P[2], P[3]);
    }
    *(float2*)&OUT[ row      * C + col] = v0;
    *(float2*)&OUT[(row + 8) * C + col] = v1;
}

extern "C" void kernel_launch(void* const* d_in, const int* in_sizes, int n_in,
                              void* d_out, int out_size)
{
    // metadata order: x, Wq, Wk1, Wk2, Wv1, Wv2, Wc
    const float* x   = (const float*)d_in[0];
    const float* Wv1 = (const float*)d_in[4];
    const float* Wv2 = (const float*)d_in[5];
    const float* Wc  = (const float*)d_in[6];
    float* out = (float*)d_out;

    float* tmp = nullptr;
    cudaGetSymbolAddress((void**)&tmp, g_tmp);

    const int sm1 = 2 * 6 * TIER * 4;   // 99072 B
    const int sm2 = 2 * 4 * TIER * 4;   // 66048 B
    cudaFuncSetAttribute(gemm_mma_kernel<true>,
                         cudaFuncAttributeMaxDynamicSharedMemorySize, sm1);
    cudaFuncSetAttribute(gemm_mma_kernel<false>,
                         cudaFuncAttributeMaxDynamicSharedMemorySize, sm2);

    dim3 grid(T / 32, C / 32);   // 8 x 16 = 128 CTAs
    gemm_mma_kernel<true ><<<grid, 256, sm1>>>(x,   Wv1, Wv2,     tmp);
    gemm_mma_kernel<false><<<grid, 256, sm2>>>(tmp, Wc,  nullptr, out);
}

// round 13
// speedup vs baseline: 1.1448x; 1.1448x over previous
#include <cuda_runtime.h>
#include <cuda_bf16.h>
#include <cstdint>

// TrueHigherOrderAttention — degenerate-mask reduction.
// The reference mask forces j==i and k==i, so the (j,k) softmax is an exact
// one-hot at (i,i,i):   out = ((x @ Wv1^T) .* (x @ Wv2^T)) @ Wc^T
//
// R13: tf32 -> bf16 m16n8k16 with 2-term decomposition (hi + lo residual;
// D = Ah*Bh + Ah*Bl + Al*Bh), ldmatrix fragment loads (LDSM, conflict-free,
// RS=36-word rows), conflict-free STS.64 loader (one row per half-warp).
// Halves MMA count, smem bytes, STS and fragment-load traffic vs the tf32
// kernel. Structure otherwise identical to the 21.2us best: 2 launches,
// 128 CTAs, double-buffered smem, fragment pipeline, parity accumulators.

constexpr int T     = 256;
constexpr int C     = 512;
constexpr int KC    = 64;          // k floats per chunk
constexpr int NCH   = 8;
constexpr int RS    = 36;          // row stride in 32-bit words (64 bf16 + pad)
constexpr int TILEW = 32 * RS;     // 1152 words per tier (32 rows)

__device__ float g_tmp[T * C];

__device__ __forceinline__ void mma16(float* d, const uint32_t* a, const uint32_t* b)
{
    asm("mma.sync.aligned.m16n8k16.row.col.f32.bf16.bf16.f32 "
        "{%0,%1,%2,%3}, {%4,%5,%6,%7}, {%8,%9}, {%0,%1,%2,%3};"
        : "+f"(d[0]), "+f"(d[1]), "+f"(d[2]), "+f"(d[3])
        : "r"(a[0]), "r"(a[1]), "r"(a[2]), "r"(a[3]),
          "r"(b[0]), "r"(b[1]));
}

__device__ __forceinline__ void ldsm4(uint32_t* r, uint32_t addr)
{
    asm volatile("ldmatrix.sync.aligned.m8n8.x4.shared.b16 {%0,%1,%2,%3}, [%4];"
                 : "=r"(r[0]), "=r"(r[1]), "=r"(r[2]), "=r"(r[3]) : "r"(addr));
}
__device__ __forceinline__ void ldsm2(uint32_t* r, uint32_t addr)
{
    asm volatile("ldmatrix.sync.aligned.m8n8.x2.shared.b16 {%0,%1}, [%2];"
                 : "=r"(r[0]), "=r"(r[1]) : "r"(addr));
}

// OUT = (X @ W1^T) [ .* (X @ W2^T) if DUAL ]  on a 32x32 tile, 2xBF16 3-term.
// X: [M x C] row-major; W: [C x C] row-major (output col n = row n of W).
template <bool DUAL>
__global__ __launch_bounds__(256)
void gemm_bf16_kernel(const float* __restrict__ X,
                      const float* __restrict__ W1,
                      const float* __restrict__ W2,
                      float* __restrict__ OUT)
{
    extern __shared__ uint32_t sm[];
    constexpr int NTILE = DUAL ? 3 : 2;
    constexpr int BUFW  = NTILE * 2 * TILEW;   // words per double-buffer half
    // tier layout (words): A_hi 0, A_lo 1*TILEW, B1_hi 2*, B1_lo 3*, B2_hi 4*, B2_lo 5*

    const int i0   = blockIdx.x * 32;
    const int n0   = blockIdx.y * 32;
    const int tid  = threadIdx.x;
    const int lane = tid & 31;
    const int wid  = tid >> 5;

    // ---- loader: q = tid&15 (float4 within chunk), rows 2*(tid>>4)+it ----
    const int lq = tid & 15;
    const int lr = (tid >> 4) * 2;

    float4 xr[2], w1r[2], w2r[2];
    auto gload = [&](int kb) {
#pragma unroll
        for (int it = 0; it < 2; it++) {
            xr [it] = *(const float4*)&X [(i0 + lr + it) * C + kb + 4 * lq];
            w1r[it] = *(const float4*)&W1[(n0 + lr + it) * C + kb + 4 * lq];
            if (DUAL)
                w2r[it] = *(const float4*)&W2[(n0 + lr + it) * C + kb + 4 * lq];
        }
    };

    // split float4 -> bf16 hi pair-words + lo residual pair-words; STS.64 each.
    // Half-warp lanes share a row, q=0..15 -> word starts 2q: conflict-free.
    auto stile = [&](uint32_t* tile, const float4& v, int it) {
        const __nv_bfloat162 h0 = __floats2bfloat162_rn(v.x, v.y);
        const __nv_bfloat162 h1 = __floats2bfloat162_rn(v.z, v.w);
        const float lx = v.x - __bfloat162float(h0.x);
        const float ly = v.y - __bfloat162float(h0.y);
        const float lz = v.z - __bfloat162float(h1.x);
        const float lw = v.w - __bfloat162float(h1.y);
        const __nv_bfloat162 l0 = __floats2bfloat162_rn(lx, ly);
        const __nv_bfloat162 l1 = __floats2bfloat162_rn(lz, lw);
        uint32_t* dst = tile + (lr + it) * RS + 2 * lq;
        *(uint2*)dst           = make_uint2(*(const uint32_t*)&h0, *(const uint32_t*)&h1);
        *(uint2*)(dst + TILEW) = make_uint2(*(const uint32_t*)&l0, *(const uint32_t*)&l1);
    };

    auto split_sts = [&](uint32_t* buf) {
#pragma unroll
        for (int it = 0; it < 2; it++) {
            stile(buf,             xr [it], it);
            stile(buf + 2 * TILEW, w1r[it], it);
            if (DUAL) stile(buf + 4 * TILEW, w2r[it], it);
        }
    };

    // ---- compute mapping: 8 warps = 2(m) x 4(n); warp tile m16 x n8 x k16 ----
    const int M0 = (wid >> 2) * 16;
    const int N0 = (wid & 3) * 8;
    // ldmatrix lane pointers (word offsets within a tier)
    const int aoff = (M0 + (lane & 15)) * RS + 4 * (lane >> 4);
    const int boff = (N0 + (lane & 7)) * RS + 4 * ((lane >> 3) & 1);

    const uint32_t smbase = (uint32_t)__cvta_generic_to_shared(sm);

    struct Frag {
        uint32_t Ah[4], Al[4], B1h[2], B1l[2], B2h[2], B2l[2];
    };
    Frag fr[2];

    auto ldfrag = [&](uint32_t bufb, int s, Frag& f) {
        const uint32_t so = 32 * s;   // 8 words per k16 step
        ldsm4(f.Ah, bufb + 4 * aoff + so);
        ldsm4(f.Al, bufb + 4 * (TILEW + aoff) + so);
        ldsm2(f.B1h, bufb + 4 * (2 * TILEW + boff) + so);
        ldsm2(f.B1l, bufb + 4 * (3 * TILEW + boff) + so);
        if (DUAL) {
            ldsm2(f.B2h, bufb + 4 * (4 * TILEW + boff) + so);
            ldsm2(f.B2l, bufb + 4 * (5 * TILEW + boff) + so);
        }
    };

    // parity-split accumulators: [step parity][term][4]
    float p[2][3][4] = {}, q[2][3][4] = {};

    // ---- prologue: fill buffer 0 ----
    gload(0);
    split_sts(sm);
    __syncthreads();

    for (int ch = 0; ch < NCH; ch++) {
        const uint32_t bufb = smbase + (ch & 1) * (BUFW * 4);
        if (ch + 1 < NCH) gload((ch + 1) * KC);   // LDG early, long latency

        ldfrag(bufb, 0, fr[0]);
#pragma unroll
        for (int s = 0; s < 4; s++) {
            if (s < 3) ldfrag(bufb, s + 1, fr[(s + 1) & 1]);
            Frag& f = fr[s & 1];
            const int par = s & 1;
            mma16(p[par][0], f.Ah, f.B1h);
            if (DUAL) mma16(q[par][0], f.Ah, f.B2h);
            mma16(p[par][1], f.Ah, f.B1l);
            if (DUAL) mma16(q[par][1], f.Ah, f.B2l);
            mma16(p[par][2], f.Al, f.B1h);
            if (DUAL) mma16(q[par][2], f.Al, f.B2h);
        }

        if (ch + 1 < NCH) {
            split_sts(sm + ((ch + 1) & 1) * BUFW);
            __syncthreads();
        }
    }

    // ---- epilogue: merge parities + terms, (optional) product, store ----
    float P[4], Q[4];
#pragma unroll
    for (int i = 0; i < 4; i++) {
        P[i] = (p[0][0][i] + p[1][0][i])
             + (p[0][1][i] + p[1][1][i])
             + (p[0][2][i] + p[1][2][i]);
        if (DUAL)
            Q[i] = (q[0][0][i] + q[1][0][i])
                 + (q[0][1][i] + q[1][1][i])
                 + (q[0][2][i] + q[1][2][i]);
    }
    const int row = i0 + M0 + (lane >> 2);
    const int col = n0 + N0 + 2 * (lane & 3);
    float2 v0, v1;
    if (DUAL) {
        v0 = make_float2(P[0] * Q[0], P[1] * Q[1]);
        v1 = make_float2(P[2] * Q[2], P[3] * Q[3]);
    } else {
        v0 = make_float2(P[0], P[1]);
        v1 = make_float2(P[2], P[3]);
    }
    *(float2*)&OUT[ row      * C + col] = v0;
    *(float2*)&OUT[(row + 8) * C + col] = v1;
}

extern "C" void kernel_launch(void* const* d_in, const int* in_sizes, int n_in,
                              void* d_out, int out_size)
{
    // metadata order: x, Wq, Wk1, Wk2, Wv1, Wv2, Wc
    const float* x   = (const float*)d_in[0];
    const float* Wv1 = (const float*)d_in[4];
    const float* Wv2 = (const float*)d_in[5];
    const float* Wc  = (const float*)d_in[6];
    float* out = (float*)d_out;

    float* tmp = nullptr;
    cudaGetSymbolAddress((void**)&tmp, g_tmp);

    const int sm1 = 2 * 6 * TILEW * 4;   // 55296 B (double-buffer, 3 tiles x 2 tiers)
    const int sm2 = 2 * 4 * TILEW * 4;   // 36864 B
    cudaFuncSetAttribute(gemm_bf16_kernel<true>,
                         cudaFuncAttributeMaxDynamicSharedMemorySize, sm1);
    cudaFuncSetAttribute(gemm_bf16_kernel<false>,
                         cudaFuncAttributeMaxDynamicSharedMemorySize, sm2);

    dim3 grid(T / 32, C / 32);   // 8 x 16 = 128 CTAs
    gemm_bf16_kernel<true ><<<grid, 256, sm1>>>(x,   Wv1, Wv2,     tmp);
    gemm_bf16_kernel<false><<<grid, 256, sm2>>>(tmp, Wc,  nullptr, out);
}

// round 14
// speedup vs baseline: 1.2576x; 1.0985x over previous
#include <cuda_runtime.h>
#include <cuda_bf16.h>
#include <cstdint>

// TrueHigherOrderAttention — degenerate-mask reduction.
// The reference mask forces j==i and k==i, so the (j,k) softmax is an exact
// one-hot at (i,i,i):   out = ((x @ Wv1^T) .* (x @ Wv2^T)) @ Wc^T
//
// R14 = R13 (18.6us: bf16 m16n8k16 3-term decomposition, ldmatrix, RS=36
// conflict-free smem, double buffer, frag pipeline, parity accumulators)
// with 16x32 CTA tiles / 128 threads / 256 CTAs: TWO co-resident CTAs per
// SM so two independent serial chunk-chains overlap each other's LDG/LDSM/
// barrier stalls (the flat ~12us stage2 floor was one serial chain per SM).

constexpr int T     = 256;
constexpr int C     = 512;
constexpr int KC    = 64;          // k floats per chunk
constexpr int NCH   = 8;
constexpr int RS    = 36;          // row stride in 32-bit words (64 bf16 + pad)
constexpr int AW    = 16 * RS;     // A tier words (16 rows)
constexpr int BW    = 32 * RS;     // B tier words (32 rows)

__device__ float g_tmp[T * C];

__device__ __forceinline__ void mma16(float* d, const uint32_t* a, const uint32_t* b)
{
    asm("mma.sync.aligned.m16n8k16.row.col.f32.bf16.bf16.f32 "
        "{%0,%1,%2,%3}, {%4,%5,%6,%7}, {%8,%9}, {%0,%1,%2,%3};"
        : "+f"(d[0]), "+f"(d[1]), "+f"(d[2]), "+f"(d[3])
        : "r"(a[0]), "r"(a[1]), "r"(a[2]), "r"(a[3]),
          "r"(b[0]), "r"(b[1]));
}

__device__ __forceinline__ void ldsm4(uint32_t* r, uint32_t addr)
{
    asm volatile("ldmatrix.sync.aligned.m8n8.x4.shared.b16 {%0,%1,%2,%3}, [%4];"
                 : "=r"(r[0]), "=r"(r[1]), "=r"(r[2]), "=r"(r[3]) : "r"(addr));
}
__device__ __forceinline__ void ldsm2(uint32_t* r, uint32_t addr)
{
    asm volatile("ldmatrix.sync.aligned.m8n8.x2.shared.b16 {%0,%1}, [%2];"
                 : "=r"(r[0]), "=r"(r[1]) : "r"(addr));
}

// OUT = (X @ W1^T) [ .* (X @ W2^T) if DUAL ]  on a 16x32 tile, 2xBF16 3-term.
// X: [M x C] row-major; W: [C x C] row-major (output col n = row n of W).
template <bool DUAL>
__global__ __launch_bounds__(128, 2)
void gemm_bf16_kernel(const float* __restrict__ X,
                      const float* __restrict__ W1,
                      const float* __restrict__ W2,
                      float* __restrict__ OUT)
{
    extern __shared__ uint32_t sm[];
    // tier layout (words): A_hi 0, A_lo AW, B1_hi 2AW, B1_lo 2AW+BW,
    //                      B2_hi 2AW+2BW, B2_lo 2AW+3BW
    constexpr int B1OFF = 2 * AW;
    constexpr int B2OFF = 2 * AW + 2 * BW;
    constexpr int BUFW  = DUAL ? (2 * AW + 4 * BW) : (2 * AW + 2 * BW);

    const int i0   = blockIdx.x * 16;
    const int n0   = blockIdx.y * 32;
    const int tid  = threadIdx.x;
    const int lane = tid & 31;
    const int wid  = tid >> 5;           // 0..3

    // ---- loader: q = tid&15 (float4 within chunk row), base row tid>>4 ----
    const int lq = tid & 15;
    const int lr = tid >> 4;             // 0..7

    float4 xr[2], w1r[4], w2r[4];
    auto gload = [&](int kb) {
#pragma unroll
        for (int it = 0; it < 2; it++)
            xr[it] = *(const float4*)&X[(i0 + lr + 8 * it) * C + kb + 4 * lq];
#pragma unroll
        for (int it = 0; it < 4; it++) {
            w1r[it] = *(const float4*)&W1[(n0 + lr + 8 * it) * C + kb + 4 * lq];
            if (DUAL)
                w2r[it] = *(const float4*)&W2[(n0 + lr + 8 * it) * C + kb + 4 * lq];
        }
    };

    // split float4 -> bf16 hi pair-words + lo residual; STS.64 each tier.
    // Phase = 16 lanes sharing one row, words 2q..2q+1 -> conflict-free.
    auto stile = [&](uint32_t* tile, int tierw, const float4& v, int row) {
        const __nv_bfloat162 h0 = __floats2bfloat162_rn(v.x, v.y);
        const __nv_bfloat162 h1 = __floats2bfloat162_rn(v.z, v.w);
        const float lx = v.x - __bfloat162float(h0.x);
        const float ly = v.y - __bfloat162float(h0.y);
        const float lz = v.z - __bfloat162float(h1.x);
        const float lw = v.w - __bfloat162float(h1.y);
        const __nv_bfloat162 l0 = __floats2bfloat162_rn(lx, ly);
        const __nv_bfloat162 l1 = __floats2bfloat162_rn(lz, lw);
        uint32_t* dst = tile + row * RS + 2 * lq;
        *(uint2*)dst           = make_uint2(*(const uint32_t*)&h0, *(const uint32_t*)&h1);
        *(uint2*)(dst + tierw) = make_uint2(*(const uint32_t*)&l0, *(const uint32_t*)&l1);
    };

    auto split_sts = [&](uint32_t* buf) {
#pragma unroll
        for (int it = 0; it < 2; it++)
            stile(buf, AW, xr[it], lr + 8 * it);
#pragma unroll
        for (int it = 0; it < 4; it++) {
            stile(buf + B1OFF, BW, w1r[it], lr + 8 * it);
            if (DUAL) stile(buf + B2OFF, BW, w2r[it], lr + 8 * it);
        }
    };

    // ---- compute mapping: 4 warps = 4(n); warp tile m16 x n8 x k16 ----
    const int N0 = wid * 8;
    const int aoff = (lane & 15) * RS + 4 * (lane >> 4);
    const int boff = (N0 + (lane & 7)) * RS + 4 * ((lane >> 3) & 1);

    const uint32_t smbase = (uint32_t)__cvta_generic_to_shared(sm);

    struct Frag {
        uint32_t Ah[4], Al[4], B1h[2], B1l[2], B2h[2], B2l[2];
    };
    Frag fr[2];

    auto ldfrag = [&](uint32_t bufb, int s, Frag& f) {
        const uint32_t so = 32 * s;   // 8 words per k16 step
        ldsm4(f.Ah, bufb + 4 * aoff + so);
        ldsm4(f.Al, bufb + 4 * (AW + aoff) + so);
        ldsm2(f.B1h, bufb + 4 * (B1OFF + boff) + so);
        ldsm2(f.B1l, bufb + 4 * (B1OFF + BW + boff) + so);
        if (DUAL) {
            ldsm2(f.B2h, bufb + 4 * (B2OFF + boff) + so);
            ldsm2(f.B2l, bufb + 4 * (B2OFF + BW + boff) + so);
        }
    };

    // parity-split accumulators: [step parity][term][4]
    float p[2][3][4] = {}, q[2][3][4] = {};

    // ---- prologue: fill buffer 0 ----
    gload(0);
    split_sts(sm);
    __syncthreads();

    for (int ch = 0; ch < NCH; ch++) {
        const uint32_t bufb = smbase + (ch & 1) * (BUFW * 4);
        if (ch + 1 < NCH) gload((ch + 1) * KC);   // LDG early, long latency

        ldfrag(bufb, 0, fr[0]);
#pragma unroll
        for (int s = 0; s < 4; s++) {
            if (s < 3) ldfrag(bufb, s + 1, fr[(s + 1) & 1]);
            Frag& f = fr[s & 1];
            const int par = s & 1;
            mma16(p[par][0], f.Ah, f.B1h);
            if (DUAL) mma16(q[par][0], f.Ah, f.B2h);
            mma16(p[par][1], f.Ah, f.B1l);
            if (DUAL) mma16(q[par][1], f.Ah, f.B2l);
            mma16(p[par][2], f.Al, f.B1h);
            if (DUAL) mma16(q[par][2], f.Al, f.B2h);
        }

        if (ch + 1 < NCH) {
            split_sts(sm + ((ch + 1) & 1) * BUFW);
            __syncthreads();
        }
    }

    // ---- epilogue: merge parities + terms, (optional) product, store ----
    float P[4], Q[4];
#pragma unroll
    for (int i = 0; i < 4; i++) {
        P[i] = (p[0][0][i] + p[1][0][i])
             + (p[0][1][i] + p[1][1][i])
             + (p[0][2][i] + p[1][2][i]);
        if (DUAL)
            Q[i] = (q[0][0][i] + q[1][0][i])
                 + (q[0][1][i] + q[1][1][i])
                 + (q[0][2][i] + q[1][2][i]);
    }
    const int row = i0 + (lane >> 2);
    const int col = n0 + N0 + 2 * (lane & 3);
    float2 v0, v1;
    if (DUAL) {
        v0 = make_float2(P[0] * Q[0], P[1] * Q[1]);
        v1 = make_float2(P[2] * Q[2], P[3] * Q[3]);
    } else {
        v0 = make_float2(P[0], P[1]);
        v1 = make_float2(P[2], P[3]);
    }
    *(float2*)&OUT[ row      * C + col] = v0;
    *(float2*)&OUT[(row + 8) * C + col] = v1;
}

extern "C" void kernel_launch(void* const* d_in, const int* in_sizes, int n_in,
                              void* d_out, int out_size)
{
    // metadata order: x, Wq, Wk1, Wk2, Wv1, Wv2, Wc
    const float* x   = (const float*)d_in[0];
    const float* Wv1 = (const float*)d_in[4];
    const float* Wv2 = (const float*)d_in[5];
    const float* Wc  = (const float*)d_in[6];
    float* out = (float*)d_out;

    float* tmp = nullptr;
    cudaGetSymbolAddress((void**)&tmp, g_tmp);

    const int sm1 = 2 * (2 * AW + 4 * BW) * 4;   // 46080 B (double-buffered)
    const int sm2 = 2 * (2 * AW + 2 * BW) * 4;   // 27648 B
    cudaFuncSetAttribute(gemm_bf16_kernel<true>,
                         cudaFuncAttributeMaxDynamicSharedMemorySize, sm1);
    cudaFuncSetAttribute(gemm_bf16_kernel<false>,
                         cudaFuncAttributeMaxDynamicSharedMemorySize, sm2);

    dim3 grid(T / 16, C / 32);   // 16 x 16 = 256 CTAs -> 2 per SM
    gemm_bf16_kernel<true ><<<grid, 128, sm1>>>(x,   Wv1, Wv2,     tmp);
    gemm_bf16_kernel<false><<<grid, 128, sm2>>>(tmp, Wc,  nullptr, out);
}